// round 13
// baseline (speedup 1.0000x reference)
#include <cuda_runtime.h>
#include <math.h>
#include <stdio.h>
#include <assert.h>

#define Vv 30000
#define Ee 300
#define Hd 300
#define G4 1200
#define Td 9
#define Bd 256
#define Sd 256

#define HT 20    // h per block (15 tiles * 20 = 300)
#define NHT 15
#define BT 64    // batch per block
#define NBT 4

// ---- scratch (device globals) ----
__device__ float  g_table_f[(size_t)Vv * G4];
__device__ float  g_table_b[(size_t)Vv * G4];
__device__ float  g_hf[(size_t)Sd * Hd * Bd];   // layout [time][h][b]
__device__ float  g_hb[(size_t)Sd * Hd * Bd];
__device__ double g_em[(size_t)Sd * Bd * Td];
__device__ unsigned char g_bp[(size_t)(Sd - 1) * Bd * Td];
__device__ unsigned g_bar2[512];                 // [g*64]=cnt, [g*64+32]=flag
__device__ int g_pad_sink;

__device__ __forceinline__ float clampg(float v) {
    return fmaxf(fminf(v, 30.f), -30.f);
}

__device__ __forceinline__ void fma2(unsigned long long& d,
                                     unsigned long long a, unsigned long long b) {
    asm("fma.rn.f32x2 %0, %1, %2, %0;" : "+l"(d) : "l"(a), "l"(b));
}
__device__ __forceinline__ float2 u2f(unsigned long long v) {
    float2 r;
    asm("mov.b64 {%0, %1}, %2;" : "=f"(r.x), "=f"(r.y) : "l"(v));
    return r;
}

struct SizePack { int n; int v[16]; };
__global__ void bad_layout_kernel(SizePack sp)
{
    printf("[diag] LAYOUT MISMATCH n_in=%d sizes:", sp.n);
    for (int i = 0; i < 16 && i < sp.n; i++) printf(" %d", sp.v[i]);
    printf("\n");
    assert(0);
}

__global__ void zero_bar_kernel()
{
    if (threadIdx.x < 512) g_bar2[threadIdx.x] = 0;
}

// tiny pad kernel: shifts launch indices so ncu (-s 5 -c 1) captures persist
__global__ void pad_kernel(int v) { if (threadIdx.x == 0) g_pad_sink = v; }

// ============================================================
// Phase 1: vocab gate table (128x128 tile, 8x8 micro, f32x2).
// ============================================================
__global__ void __launch_bounds__(256)
table_gemm(const float* __restrict__ A,
           const float* __restrict__ Wf, const float* __restrict__ Wb,
           const float* __restrict__ b1f, const float* __restrict__ b2f,
           const float* __restrict__ b1b, const float* __restrict__ b2b)
{
    int dir = blockIdx.z;
    const float* W  = dir ? Wb  : Wf;
    const float* b1 = dir ? b1b : b1f;
    const float* b2 = dir ? b2b : b2f;
    float* C = dir ? g_table_b : g_table_f;

    __shared__ __align__(16) float As2[16 * 264];
    __shared__ __align__(16) float Wsm[16 * 132];

    int n0 = blockIdx.x * 128;
    int m0 = blockIdx.y * 128;
    int tid = threadIdx.x;
    int tx = tid & 15;
    int ty = tid >> 4;
    int r  = tid & 127;
    int part = tid >> 7;

    unsigned long long acc[8][4];
#pragma unroll
    for (int i = 0; i < 8; i++)
#pragma unroll
        for (int p = 0; p < 4; p++) acc[i][p] = 0ull;

    for (int k0 = 0; k0 < Ee; k0 += 16) {
        __syncthreads();
        {
            int m = m0 + r;
#pragma unroll
            for (int j = 0; j < 2; j++) {
                int k = k0 + part * 8 + j * 4;
                float4 v = make_float4(0.f, 0.f, 0.f, 0.f);
                if (m < Vv && k + 3 < Ee)
                    v = *(const float4*)&A[(size_t)m * Ee + k];
                int kk = part * 8 + j * 4;
                float* dst0 = &As2[kk * 264 + 2 * r];
                *(float2*)(dst0)           = make_float2(v.x, v.x);
                *(float2*)(dst0 + 264)     = make_float2(v.y, v.y);
                *(float2*)(dst0 + 2 * 264) = make_float2(v.z, v.z);
                *(float2*)(dst0 + 3 * 264) = make_float2(v.w, v.w);
            }
        }
        {
            int n = n0 + r;
#pragma unroll
            for (int j = 0; j < 2; j++) {
                int k = k0 + part * 8 + j * 4;
                float4 v = make_float4(0.f, 0.f, 0.f, 0.f);
                if (n < G4 && k + 3 < Ee)
                    v = *(const float4*)&W[(size_t)n * Ee + k];
                int kk = part * 8 + j * 4;
                Wsm[kk * 132 + r]           = v.x;
                Wsm[(kk + 1) * 132 + r]     = v.y;
                Wsm[(kk + 2) * 132 + r]     = v.z;
                Wsm[(kk + 3) * 132 + r]     = v.w;
            }
        }
        __syncthreads();
#pragma unroll 4
        for (int kk = 0; kk < 16; kk++) {
            const float* arow = &As2[kk * 264 + ty * 16];
            const float* wrow = &Wsm[kk * 132 + tx * 8];
            ulonglong2 a01 = *(const ulonglong2*)(arow);
            ulonglong2 a23 = *(const ulonglong2*)(arow + 4);
            ulonglong2 a45 = *(const ulonglong2*)(arow + 8);
            ulonglong2 a67 = *(const ulonglong2*)(arow + 12);
            ulonglong2 w03 = *(const ulonglong2*)(wrow);
            ulonglong2 w47 = *(const ulonglong2*)(wrow + 4);
            unsigned long long av[8] = {a01.x, a01.y, a23.x, a23.y,
                                        a45.x, a45.y, a67.x, a67.y};
            unsigned long long wv[4] = {w03.x, w03.y, w47.x, w47.y};
#pragma unroll
            for (int i = 0; i < 8; i++)
#pragma unroll
                for (int p = 0; p < 4; p++) fma2(acc[i][p], av[i], wv[p]);
        }
    }

    float bias[8];
#pragma unroll
    for (int j = 0; j < 8; j++) {
        int n = n0 + tx * 8 + j;
        bias[j] = (n < G4) ? (b1[n] + b2[n]) : 0.f;
    }
#pragma unroll
    for (int i = 0; i < 8; i++) {
        int m = m0 + ty * 8 + i;
        if (m >= Vv) continue;
        float vals[8];
#pragma unroll
        for (int p = 0; p < 4; p++) {
            float2 u = u2f(acc[i][p]);
            vals[2 * p]     = u.x + bias[2 * p];
            vals[2 * p + 1] = u.y + bias[2 * p + 1];
        }
        int nb = n0 + tx * 8;
        if (nb + 7 < G4) {
            *(float4*)&C[(size_t)m * G4 + nb]     = make_float4(vals[0], vals[1], vals[2], vals[3]);
            *(float4*)&C[(size_t)m * G4 + nb + 4] = make_float4(vals[4], vals[5], vals[6], vals[7]);
        } else {
#pragma unroll
            for (int j = 0; j < 8; j++)
                if (nb + j < G4) C[(size_t)m * G4 + nb + j] = vals[j];
        }
    }
}

// ============================================================
// Phase 2: PERSISTENT bidirectional LSTM, v3.
// Accumulators in (b,b) pairs; W duplicated ONCE in smem (192KB, static
// across all 256 steps); h staged plain (no duplication, half traffic).
// Warp mapping b-major: w-loads broadcast (1 phase), h-loads 2 phases.
// grid (15,4,2)=120 resident blocks, 320 threads.
// ============================================================
__global__ void __launch_bounds__(320, 1)
lstm_persist(const int* __restrict__ x,
             const float* __restrict__ whhf, const float* __restrict__ whhb)
{
    extern __shared__ __align__(16) float smem[];
    float* Ws2  = smem;                      // [300][20][8] g-duplicated: 192,000B
    float* Hbuf0 = smem + 48000;             // [60][64]: 15,360B
    float* Hbuf1 = smem + 48000 + 3840;      // 15,360B
    int*   stok  = (int*)(smem + 48000 + 7680);   // 64 tokens

    int htile = blockIdx.x;
    int btile = blockIdx.y;
    int dir   = blockIdx.z;
    int h0 = htile * HT;
    int b0 = btile * BT;

    const float* whh = dir ? whhb : whhf;
    const float* tbl = dir ? g_table_b : g_table_f;
    float* hbase = dir ? g_hb : g_hf;
    unsigned* cnt = &g_bar2[(dir * 4 + btile) * 64];
    volatile unsigned* flag = (volatile unsigned*)&g_bar2[(dir * 4 + btile) * 64 + 32];

    int tid = threadIdx.x;
    int bq = tid & 15;        // b-quad (0..15) -> 4 b's
    int hx = tid >> 4;        // h lane (0..19)
    int h  = h0 + hx;

    // load W once, gate-duplicated: Ws2[k*160 + hx*8 + g*2 + {0,1}]
    for (int idx = tid; idx < HT * 4 * Hd; idx += 320) {
        int k = idx % Hd;
        int q = idx / Hd;            // 0..79
        int hl = q >> 2, g = q & 3;
        float v = whh[((size_t)g * Hd + h0 + hl) * Hd + k];
        float* d = &Ws2[(size_t)k * 160 + hl * 8 + g * 2];
        d[0] = v; d[1] = v;
    }

    float cst[4] = {0.f, 0.f, 0.f, 0.f};

    for (int s = 0; s < Sd; s++) {
        int time = dir ? (Sd - 1 - s) : s;

        if (tid < 64) {
            int t = x[(b0 + tid) * Sd + time];
            stok[tid] = ((unsigned)t < (unsigned)Vv) ? t : 0;
        }
        __syncthreads();   // tokens visible; also covers Ws2 load at s==0

        // prefetch table rows (consumed in epilogue)
        float tv[4][4];
#pragma unroll
        for (int i = 0; i < 4; i++) {
            const float* trow = tbl + (size_t)stok[bq * 4 + i] * G4 + h;
#pragma unroll
            for (int g = 0; g < 4; g++) tv[i][g] = __ldg(trow + g * Hd);
        }

        // acc[g][bp]: gate g for b-pair bp (b = bq*4 + 2*bp + {0,1})
        unsigned long long acc[4][2] = {{0ull,0ull},{0ull,0ull},{0ull,0ull},{0ull,0ull}};

        if (s > 0) {
            int ptime = dir ? (time + 1) : (time - 1);
            const float* hprev = hbase + (size_t)ptime * Hd * Bd + b0;

            // stage chunk 0 (plain copy, no duplication): 3 float4/thread
#pragma unroll
            for (int l = 0; l < 3; l++) {
                int j = tid + l * 320;
                int c = j >> 4, r = j & 15;
                *(float4*)&Hbuf0[c * 64 + r * 4] =
                    *(const float4*)&hprev[(size_t)c * Bd + r * 4];
            }
            float* bufs[2] = {Hbuf0, Hbuf1};
            int cur = 0;
#pragma unroll
            for (int chunk = 0; chunk < 5; chunk++) {
                __syncthreads();
                if (chunk < 4) {
                    const float* hp = hprev + (size_t)((chunk + 1) * 60) * Bd;
                    float* dst = bufs[cur ^ 1];
#pragma unroll
                    for (int l = 0; l < 3; l++) {
                        int j = tid + l * 320;
                        int c = j >> 4, r = j & 15;
                        *(float4*)&dst[c * 64 + r * 4] =
                            *(const float4*)&hp[(size_t)c * Bd + r * 4];
                    }
                }
                const float* wsb = Ws2 + (size_t)(chunk * 60) * 160 + hx * 8;
                const float* hb  = bufs[cur] + bq * 4;
#pragma unroll 4
                for (int kk = 0; kk < 60; kk++) {
                    ulonglong2 w01 = *(const ulonglong2*)(wsb + (size_t)kk * 160);
                    ulonglong2 w23 = *(const ulonglong2*)(wsb + (size_t)kk * 160 + 4);
                    ulonglong2 hv  = *(const ulonglong2*)(hb + kk * 64);
                    fma2(acc[0][0], hv.x, w01.x); fma2(acc[0][1], hv.y, w01.x);
                    fma2(acc[1][0], hv.x, w01.y); fma2(acc[1][1], hv.y, w01.y);
                    fma2(acc[2][0], hv.x, w23.x); fma2(acc[2][1], hv.y, w23.x);
                    fma2(acc[3][0], hv.x, w23.y); fma2(acc[3][1], hv.y, w23.y);
                }
                cur ^= 1;
            }
        }

        // epilogue: gates -> activations -> h,c  (i = local b index 0..3)
        float hnew[4];
#pragma unroll
        for (int i = 0; i < 4; i++) {
            int bp = i >> 1, e = i & 1;
            float2 gi = u2f(acc[0][bp]);
            float2 gf = u2f(acc[1][bp]);
            float2 gg2 = u2f(acc[2][bp]);
            float2 go = u2f(acc[3][bp]);
            float ai = clampg((e ? gi.y : gi.x) + tv[i][0]);
            float af = clampg((e ? gf.y : gf.x) + tv[i][1]);
            float ag = clampg((e ? gg2.y : gg2.x) + tv[i][2]);
            float ao = clampg((e ? go.y : go.x) + tv[i][3]);
            float ig = 1.f / (1.f + expf(-ai));
            float fg = 1.f / (1.f + expf(-af));
            float gg = tanhf(ag);
            float og = 1.f / (1.f + expf(-ao));
            float cnew = fg * cst[i] + ig * gg;
            cst[i] = cnew;
            hnew[i] = og * tanhf(clampg(cnew));
        }
        *(float4*)&hbase[((size_t)time * Hd + h) * Bd + b0 + bq * 4] =
            make_float4(hnew[0], hnew[1], hnew[2], hnew[3]);

        // flag-release group barrier (15 blocks sharing dir+btile)
        if (s < Sd - 1) {
            __syncthreads();
            if (tid == 0) {
                __threadfence();
                unsigned v = atomicAdd(cnt, 1u) + 1u;
                if (v == (unsigned)NHT * (unsigned)(s + 1)) {
                    atomicExch((unsigned*)flag, (unsigned)(s + 1));
                } else {
                    while (*flag < (unsigned)(s + 1)) { }
                }
                __threadfence();
            }
            __syncthreads();
        }
    }
}

// ============================================================
// Phase 3a: emissions, fp64 accumulation. Block per s, thread per b.
// ============================================================
__global__ void __launch_bounds__(256)
emis_kernel(const float* __restrict__ wproj, const float* __restrict__ bproj)
{
    __shared__ float wp[Td * 2 * Hd];
    int s = blockIdx.x;
    int b = threadIdx.x;
    for (int i = threadIdx.x; i < Td * 2 * Hd; i += blockDim.x) wp[i] = wproj[i];
    __syncthreads();

    const float* f  = g_hf + (size_t)s * Hd * Bd;
    const float* bk = g_hb + (size_t)s * Hd * Bd;
    double acc[Td] = {};
    for (int j = 0; j < Hd; j++) {
        double v = (double)f[(size_t)j * Bd + b];
#pragma unroll
        for (int t = 0; t < Td; t++) acc[t] += v * (double)wp[t * 2 * Hd + j];
    }
    for (int j = 0; j < Hd; j++) {
        double v = (double)bk[(size_t)j * Bd + b];
#pragma unroll
        for (int t = 0; t < Td; t++) acc[t] += v * (double)wp[t * 2 * Hd + Hd + j];
    }
#pragma unroll
    for (int t = 0; t < Td; t++)
        g_em[((size_t)s * Bd + b) * Td + t] = acc[t] + (double)bproj[t];
}

// ============================================================
// Phase 3b: Viterbi DP + backtrack, fp64, float32 tag output.
// ============================================================
__global__ void viterbi_kernel(const float* __restrict__ start_t, const float* __restrict__ end_t,
                               const float* __restrict__ trans, float* __restrict__ out)
{
    __shared__ double tr[Td][Td];
    if (threadIdx.x < Td * Td)
        tr[threadIdx.x / Td][threadIdx.x % Td] = (double)trans[threadIdx.x];
    __syncthreads();
    int b = blockIdx.x * blockDim.x + threadIdx.x;
    if (b >= Bd) return;

    double sc[Td];
#pragma unroll
    for (int t = 0; t < Td; t++)
        sc[t] = (double)start_t[t] + g_em[(size_t)b * Td + t];

    for (int s = 1; s < Sd; s++) {
        const double* em = &g_em[((size_t)s * Bd + b) * Td];
        double ns[Td];
#pragma unroll
        for (int tn = 0; tn < Td; tn++) {
            double best = sc[0] + tr[0][tn];
            int arg = 0;
#pragma unroll
            for (int tp = 1; tp < Td; tp++) {
                double v = sc[tp] + tr[tp][tn];
                if (v > best) { best = v; arg = tp; }
            }
            ns[tn] = best + em[tn];
            g_bp[((size_t)(s - 1) * Bd + b) * Td + tn] = (unsigned char)arg;
        }
#pragma unroll
        for (int t = 0; t < Td; t++) sc[t] = ns[t];
    }

    int last = 0;
    double best = sc[0] + (double)end_t[0];
#pragma unroll
    for (int t = 1; t < Td; t++) {
        double v = sc[t] + (double)end_t[t];
        if (v > best) { best = v; last = t; }
    }
    out[b * Sd + (Sd - 1)] = (float)last;
    int tag = last;
    for (int s = Sd - 2; s >= 0; s--) {
        tag = g_bp[((size_t)s * Bd + b) * Td + tag];
        out[b * Sd + s] = (float)tag;
    }
}

// ============================================================
extern "C" void kernel_launch(void* const* d_in, const int* in_sizes, int n_in,
                              void* d_out, int out_size)
{
    static const int expA[15] = {65536, 9000000, 360000, 360000, 1200, 1200,
                                 360000, 360000, 1200, 1200, 5400, 9, 9, 9, 81};
    bool okA = (n_in == 15), okA4 = (n_in == 15);
    for (int i = 0; i < 15 && n_in == 15; i++) {
        if (in_sizes[i] != expA[i])     okA  = false;
        if (in_sizes[i] != expA[i] * 4) okA4 = false;
    }
    if (!okA && !okA4) {
        SizePack sp; sp.n = n_in;
        for (int i = 0; i < 16; i++) sp.v[i] = (i < n_in) ? in_sizes[i] : -1;
        bad_layout_kernel<<<1, 1>>>(sp);
        return;
    }

    const int*   x       = (const int*)  d_in[0];
    const float* emb     = (const float*)d_in[1];
    const float* wihf    = (const float*)d_in[2];
    const float* whhf    = (const float*)d_in[3];
    const float* bihf    = (const float*)d_in[4];
    const float* bhhf    = (const float*)d_in[5];
    const float* wihb    = (const float*)d_in[6];
    const float* whhb    = (const float*)d_in[7];
    const float* bihb    = (const float*)d_in[8];
    const float* bhhb    = (const float*)d_in[9];
    const float* wproj   = (const float*)d_in[10];
    const float* bproj   = (const float*)d_in[11];
    const float* start_t = (const float*)d_in[12];
    const float* end_t   = (const float*)d_in[13];
    const float* trans   = (const float*)d_in[14];
    float* out = (float*)d_out;

    zero_bar_kernel<<<1, 512>>>();                                   // launch 0

    dim3 gt((G4 + 127) / 128, (Vv + 127) / 128, 2);
    table_gemm<<<gt, 256>>>(emb, wihf, wihb, bihf, bhhf, bihb, bhhb); // launch 1

    // pads: shift persist to launch index 5 so ncu (-s 5 -c 1) captures it
    pad_kernel<<<1, 32>>>(2);                                        // launch 2
    pad_kernel<<<1, 32>>>(3);                                        // launch 3
    pad_kernel<<<1, 32>>>(4);                                        // launch 4

    int smem_bytes = (48000 + 7680 + 64) * sizeof(float);            // 222,976 B
    cudaFuncSetAttribute(lstm_persist,
                         cudaFuncAttributeMaxDynamicSharedMemorySize, smem_bytes);
    dim3 gp(NHT, NBT, 2);
    lstm_persist<<<gp, 320, smem_bytes>>>(x, whhf, whhb);            // launch 5

    emis_kernel<<<Sd, Bd>>>(wproj, bproj);                           // launch 6
    viterbi_kernel<<<2, 128>>>(start_t, end_t, trans, out);          // launch 7
}

// round 14
// speedup vs baseline: 1.0277x; 1.0277x over previous
#include <cuda_runtime.h>
#include <math.h>
#include <stdio.h>
#include <assert.h>

#define Vv 30000
#define Ee 300
#define Hd 300
#define G4 1200
#define Td 9
#define Bd 256
#define Sd 256

// ---- scratch (device globals) ----
__device__ float  g_table_f[(size_t)Vv * G4];
__device__ float  g_table_b[(size_t)Vv * G4];
__device__ float  g_hf[(size_t)Sd * Hd * Bd];   // [time][h][b]
__device__ float  g_hb[(size_t)Sd * Hd * Bd];
__device__ float  g_cf[Hd * Bd];                // [h][b]
__device__ float  g_cb[Hd * Bd];
__device__ double g_em[(size_t)Sd * Bd * Td];
__device__ unsigned char g_bp[(size_t)(Sd - 1) * Bd * Td];

__device__ __forceinline__ float clampg(float v) {
    return fmaxf(fminf(v, 30.f), -30.f);
}

__device__ __forceinline__ void fma2(unsigned long long& d,
                                     unsigned long long a, unsigned long long b) {
    asm("fma.rn.f32x2 %0, %1, %2, %0;" : "+l"(d) : "l"(a), "l"(b));
}
__device__ __forceinline__ float2 u2f(unsigned long long v) {
    float2 r;
    asm("mov.b64 {%0, %1}, %2;" : "=f"(r.x), "=f"(r.y) : "l"(v));
    return r;
}

struct SizePack { int n; int v[16]; };
__global__ void bad_layout_kernel(SizePack sp)
{
    printf("[diag] LAYOUT MISMATCH n_in=%d sizes:", sp.n);
    for (int i = 0; i < 16 && i < sp.n; i++) printf(" %d", sp.v[i]);
    printf("\n");
    assert(0);
}

// ============================================================
// Phase 1: vocab gate table (128x128 tile, 8x8 micro, f32x2).
// ============================================================
__global__ void __launch_bounds__(256)
table_gemm(const float* __restrict__ A,
           const float* __restrict__ Wf, const float* __restrict__ Wb,
           const float* __restrict__ b1f, const float* __restrict__ b2f,
           const float* __restrict__ b1b, const float* __restrict__ b2b)
{
    int dir = blockIdx.z;
    const float* W  = dir ? Wb  : Wf;
    const float* b1 = dir ? b1b : b1f;
    const float* b2 = dir ? b2b : b2f;
    float* C = dir ? g_table_b : g_table_f;

    __shared__ __align__(16) float As2[16 * 264];
    __shared__ __align__(16) float Wsm[16 * 132];

    int n0 = blockIdx.x * 128;
    int m0 = blockIdx.y * 128;
    int tid = threadIdx.x;
    int tx = tid & 15;
    int ty = tid >> 4;
    int r  = tid & 127;
    int part = tid >> 7;

    unsigned long long acc[8][4];
#pragma unroll
    for (int i = 0; i < 8; i++)
#pragma unroll
        for (int p = 0; p < 4; p++) acc[i][p] = 0ull;

    for (int k0 = 0; k0 < Ee; k0 += 16) {
        __syncthreads();
        {
            int m = m0 + r;
#pragma unroll
            for (int j = 0; j < 2; j++) {
                int k = k0 + part * 8 + j * 4;
                float4 v = make_float4(0.f, 0.f, 0.f, 0.f);
                if (m < Vv && k + 3 < Ee)
                    v = *(const float4*)&A[(size_t)m * Ee + k];
                int kk = part * 8 + j * 4;
                float* dst0 = &As2[kk * 264 + 2 * r];
                *(float2*)(dst0)           = make_float2(v.x, v.x);
                *(float2*)(dst0 + 264)     = make_float2(v.y, v.y);
                *(float2*)(dst0 + 2 * 264) = make_float2(v.z, v.z);
                *(float2*)(dst0 + 3 * 264) = make_float2(v.w, v.w);
            }
        }
        {
            int n = n0 + r;
#pragma unroll
            for (int j = 0; j < 2; j++) {
                int k = k0 + part * 8 + j * 4;
                float4 v = make_float4(0.f, 0.f, 0.f, 0.f);
                if (n < G4 && k + 3 < Ee)
                    v = *(const float4*)&W[(size_t)n * Ee + k];
                int kk = part * 8 + j * 4;
                Wsm[kk * 132 + r]           = v.x;
                Wsm[(kk + 1) * 132 + r]     = v.y;
                Wsm[(kk + 2) * 132 + r]     = v.z;
                Wsm[(kk + 3) * 132 + r]     = v.w;
            }
        }
        __syncthreads();
#pragma unroll 4
        for (int kk = 0; kk < 16; kk++) {
            const float* arow = &As2[kk * 264 + ty * 16];
            const float* wrow = &Wsm[kk * 132 + tx * 8];
            ulonglong2 a01 = *(const ulonglong2*)(arow);
            ulonglong2 a23 = *(const ulonglong2*)(arow + 4);
            ulonglong2 a45 = *(const ulonglong2*)(arow + 8);
            ulonglong2 a67 = *(const ulonglong2*)(arow + 12);
            ulonglong2 w03 = *(const ulonglong2*)(wrow);
            ulonglong2 w47 = *(const ulonglong2*)(wrow + 4);
            unsigned long long av[8] = {a01.x, a01.y, a23.x, a23.y,
                                        a45.x, a45.y, a67.x, a67.y};
            unsigned long long wv[4] = {w03.x, w03.y, w47.x, w47.y};
#pragma unroll
            for (int i = 0; i < 8; i++)
#pragma unroll
                for (int p = 0; p < 4; p++) fma2(acc[i][p], av[i], wv[p]);
        }
    }

    float bias[8];
#pragma unroll
    for (int j = 0; j < 8; j++) {
        int n = n0 + tx * 8 + j;
        bias[j] = (n < G4) ? (b1[n] + b2[n]) : 0.f;
    }
#pragma unroll
    for (int i = 0; i < 8; i++) {
        int m = m0 + ty * 8 + i;
        if (m >= Vv) continue;
        float vals[8];
#pragma unroll
        for (int p = 0; p < 4; p++) {
            float2 u = u2f(acc[i][p]);
            vals[2 * p]     = u.x + bias[2 * p];
            vals[2 * p + 1] = u.y + bias[2 * p + 1];
        }
        int nb = n0 + tx * 8;
        if (nb + 7 < G4) {
            *(float4*)&C[(size_t)m * G4 + nb]     = make_float4(vals[0], vals[1], vals[2], vals[3]);
            *(float4*)&C[(size_t)m * G4 + nb + 4] = make_float4(vals[4], vals[5], vals[6], vals[7]);
        } else {
#pragma unroll
            for (int j = 0; j < 8; j++)
                if (nb + j < G4) C[(size_t)m * G4 + nb + j] = vals[j];
        }
    }
}

// ============================================================
// Phase 2: one LSTM step (per-step launch, proven architecture).
// v4: whole W tile (16h x 4g x 300k = 76.8KB) staged ONCE per step;
// h double-buffered in 60-row chunks -> 6 syncs/step (was 20).
// Tile 16h x 64b, 256 thr; thread = 4b x 4g x 1h scalar FFMA.
// grid (19,4,2)=152.
// ============================================================
__global__ void __launch_bounds__(256)
lstm_step(int s, const int* __restrict__ x,
          const float* __restrict__ whhf, const float* __restrict__ whhb)
{
    extern __shared__ __align__(16) float smem[];
    float* Ws  = smem;            // [300][68] gate-interleaved (hl*4+g), 81.6KB
    float* Hs0 = smem + 300 * 68; // [60][68]
    float* Hs1 = Hs0 + 60 * 68;

    int dir = blockIdx.z;
    const float* whh = dir ? whhb : whhf;
    const float* tbl = dir ? g_table_b : g_table_f;
    float* hseq = dir ? g_hb : g_hf;
    float* cbuf = dir ? g_cb : g_cf;
    int time = dir ? (Sd - 1 - s) : s;

    int h0 = blockIdx.x * 16;
    int b0 = blockIdx.y * 64;
    int tid = threadIdx.x;
    int tx = tid & 15;    // h lane
    int ty = tid >> 4;    // b quad
    int h  = h0 + tx;
    int hh = (h < Hd) ? h : (Hd - 1);   // safe index for prefetch

    // token + table-row prefetch (consumed in epilogue; latency hidden)
    float tv[4][4];
#pragma unroll
    for (int i = 0; i < 4; i++) {
        int t = __ldg(&x[(b0 + ty * 4 + i) * Sd + time]);
        if ((unsigned)t >= (unsigned)Vv) t = 0;
        const float* trow = tbl + (size_t)t * G4 + hh;
#pragma unroll
        for (int g = 0; g < 4; g++) tv[i][g] = __ldg(trow + g * Hd);
    }

    float acc[4][4] = {};   // [b_i][gate]

    if (s > 0) {
        int ptime = dir ? (time + 1) : (time - 1);
        const float* hprev = hseq + (size_t)ptime * Hd * Bd + b0;

        // ---- stage whole W tile: Ws[k][hl*4+g] = whh[(g*300+h0+hl)*300+k]
        // 4800 float4 loads along k, scattered into smem.
#pragma unroll
        for (int l = 0; l < 19; l++) {
            int j = tid + l * 256;
            if (j < 4800) {
                int k4 = j % 75;
                int q  = j / 75;          // 0..63
                int hl = q >> 2, g = q & 3;
                float4 v = make_float4(0.f, 0.f, 0.f, 0.f);
                if (h0 + hl < Hd)
                    v = *(const float4*)&whh[((size_t)g * Hd + h0 + hl) * Hd + k4 * 4];
                int q4 = hl * 4 + g;
                Ws[(k4 * 4 + 0) * 68 + q4] = v.x;
                Ws[(k4 * 4 + 1) * 68 + q4] = v.y;
                Ws[(k4 * 4 + 2) * 68 + q4] = v.z;
                Ws[(k4 * 4 + 3) * 68 + q4] = v.w;
            }
        }
        // ---- stage h chunk 0
#pragma unroll
        for (int l = 0; l < 4; l++) {
            int j = tid + l * 256;
            if (j < 960) {
                int c = j >> 4, r = j & 15;
                *(float4*)&Hs0[c * 68 + r * 4] =
                    *(const float4*)&hprev[(size_t)c * Bd + r * 4];
            }
        }

        float* bufs[2] = {Hs0, Hs1};
        int cur = 0;
#pragma unroll
        for (int chunk = 0; chunk < 5; chunk++) {
            __syncthreads();
            if (chunk < 4) {
                const float* hp = hprev + (size_t)((chunk + 1) * 60) * Bd;
                float* dst = bufs[cur ^ 1];
#pragma unroll
                for (int l = 0; l < 4; l++) {
                    int j = tid + l * 256;
                    if (j < 960) {
                        int c = j >> 4, r = j & 15;
                        *(float4*)&dst[c * 68 + r * 4] =
                            *(const float4*)&hp[(size_t)c * Bd + r * 4];
                    }
                }
            }
            const float* wsb = Ws + (size_t)(chunk * 60) * 68 + tx * 4;
            const float* hb  = bufs[cur] + ty * 4;
#pragma unroll 4
            for (int kk = 0; kk < 60; kk++) {
                float4 w4 = *(const float4*)(wsb + kk * 68);
                float4 h4 = *(const float4*)(hb + kk * 68);
                float wv[4] = {w4.x, w4.y, w4.z, w4.w};
                float hv[4] = {h4.x, h4.y, h4.z, h4.w};
#pragma unroll
                for (int i = 0; i < 4; i++)
#pragma unroll
                    for (int g = 0; g < 4; g++) acc[i][g] += hv[i] * wv[g];
            }
            cur ^= 1;
        }
    }

    // epilogue
    if (h < Hd) {
        float hnew[4], cnew4[4];
        float4 cold4 = make_float4(0.f, 0.f, 0.f, 0.f);
        if (s > 0) cold4 = *(const float4*)&cbuf[(size_t)h * Bd + b0 + ty * 4];
        float coldA[4] = {cold4.x, cold4.y, cold4.z, cold4.w};
#pragma unroll
        for (int i = 0; i < 4; i++) {
            float ai = clampg(acc[i][0] + tv[i][0]);
            float af = clampg(acc[i][1] + tv[i][1]);
            float ag = clampg(acc[i][2] + tv[i][2]);
            float ao = clampg(acc[i][3] + tv[i][3]);
            float ig = 1.f / (1.f + expf(-ai));
            float fg = 1.f / (1.f + expf(-af));
            float gg = tanhf(ag);
            float og = 1.f / (1.f + expf(-ao));
            float cnew = fg * coldA[i] + ig * gg;
            cnew4[i] = cnew;
            hnew[i] = og * tanhf(clampg(cnew));
        }
        *(float4*)&cbuf[(size_t)h * Bd + b0 + ty * 4] =
            make_float4(cnew4[0], cnew4[1], cnew4[2], cnew4[3]);
        *(float4*)&hseq[((size_t)time * Hd + h) * Bd + b0 + ty * 4] =
            make_float4(hnew[0], hnew[1], hnew[2], hnew[3]);
    }
}

// ============================================================
// Phase 3a: emissions, fp64 accumulation. Block per s, thread per b.
// ============================================================
__global__ void __launch_bounds__(256)
emis_kernel(const float* __restrict__ wproj, const float* __restrict__ bproj)
{
    __shared__ float wp[Td * 2 * Hd];
    int s = blockIdx.x;
    int b = threadIdx.x;
    for (int i = threadIdx.x; i < Td * 2 * Hd; i += blockDim.x) wp[i] = wproj[i];
    __syncthreads();

    const float* f  = g_hf + (size_t)s * Hd * Bd;
    const float* bk = g_hb + (size_t)s * Hd * Bd;
    double acc[Td] = {};
    for (int j = 0; j < Hd; j++) {
        double v = (double)f[(size_t)j * Bd + b];
#pragma unroll
        for (int t = 0; t < Td; t++) acc[t] += v * (double)wp[t * 2 * Hd + j];
    }
    for (int j = 0; j < Hd; j++) {
        double v = (double)bk[(size_t)j * Bd + b];
#pragma unroll
        for (int t = 0; t < Td; t++) acc[t] += v * (double)wp[t * 2 * Hd + Hd + j];
    }
#pragma unroll
    for (int t = 0; t < Td; t++)
        g_em[((size_t)s * Bd + b) * Td + t] = acc[t] + (double)bproj[t];
}

// ============================================================
// Phase 3b: Viterbi DP + backtrack, fp64, float32 tag output.
// ============================================================
__global__ void viterbi_kernel(const float* __restrict__ start_t, const float* __restrict__ end_t,
                               const float* __restrict__ trans, float* __restrict__ out)
{
    __shared__ double tr[Td][Td];
    if (threadIdx.x < Td * Td)
        tr[threadIdx.x / Td][threadIdx.x % Td] = (double)trans[threadIdx.x];
    __syncthreads();
    int b = blockIdx.x * blockDim.x + threadIdx.x;
    if (b >= Bd) return;

    double sc[Td];
#pragma unroll
    for (int t = 0; t < Td; t++)
        sc[t] = (double)start_t[t] + g_em[(size_t)b * Td + t];

    for (int s = 1; s < Sd; s++) {
        const double* em = &g_em[((size_t)s * Bd + b) * Td];
        double ns[Td];
#pragma unroll
        for (int tn = 0; tn < Td; tn++) {
            double best = sc[0] + tr[0][tn];
            int arg = 0;
#pragma unroll
            for (int tp = 1; tp < Td; tp++) {
                double v = sc[tp] + tr[tp][tn];
                if (v > best) { best = v; arg = tp; }
            }
            ns[tn] = best + em[tn];
            g_bp[((size_t)(s - 1) * Bd + b) * Td + tn] = (unsigned char)arg;
        }
#pragma unroll
        for (int t = 0; t < Td; t++) sc[t] = ns[t];
    }

    int last = 0;
    double best = sc[0] + (double)end_t[0];
#pragma unroll
    for (int t = 1; t < Td; t++) {
        double v = sc[t] + (double)end_t[t];
        if (v > best) { best = v; last = t; }
    }
    out[b * Sd + (Sd - 1)] = (float)last;
    int tag = last;
    for (int s = Sd - 2; s >= 0; s--) {
        tag = g_bp[((size_t)s * Bd + b) * Td + tag];
        out[b * Sd + s] = (float)tag;
    }
}

// ============================================================
extern "C" void kernel_launch(void* const* d_in, const int* in_sizes, int n_in,
                              void* d_out, int out_size)
{
    static const int expA[15] = {65536, 9000000, 360000, 360000, 1200, 1200,
                                 360000, 360000, 1200, 1200, 5400, 9, 9, 9, 81};
    bool okA = (n_in == 15), okA4 = (n_in == 15);
    for (int i = 0; i < 15 && n_in == 15; i++) {
        if (in_sizes[i] != expA[i])     okA  = false;
        if (in_sizes[i] != expA[i] * 4) okA4 = false;
    }
    if (!okA && !okA4) {
        SizePack sp; sp.n = n_in;
        for (int i = 0; i < 16; i++) sp.v[i] = (i < n_in) ? in_sizes[i] : -1;
        bad_layout_kernel<<<1, 1>>>(sp);
        return;
    }

    const int*   x       = (const int*)  d_in[0];
    const float* emb     = (const float*)d_in[1];
    const float* wihf    = (const float*)d_in[2];
    const float* whhf    = (const float*)d_in[3];
    const float* bihf    = (const float*)d_in[4];
    const float* bhhf    = (const float*)d_in[5];
    const float* wihb    = (const float*)d_in[6];
    const float* whhb    = (const float*)d_in[7];
    const float* bihb    = (const float*)d_in[8];
    const float* bhhb    = (const float*)d_in[9];
    const float* wproj   = (const float*)d_in[10];
    const float* bproj   = (const float*)d_in[11];
    const float* start_t = (const float*)d_in[12];
    const float* end_t   = (const float*)d_in[13];
    const float* trans   = (const float*)d_in[14];
    float* out = (float*)d_out;

    // Phase 1: vocab gate tables
    dim3 gt((G4 + 127) / 128, (Vv + 127) / 128, 2);
    table_gemm<<<gt, 256>>>(emb, wihf, wihb, bihf, bhhf, bihb, bhhb);

    // Phase 2: 256 per-step launches
    int smem_bytes = (300 * 68 + 2 * 60 * 68) * sizeof(float);   // 114,240 B
    cudaFuncSetAttribute(lstm_step,
                         cudaFuncAttributeMaxDynamicSharedMemorySize, smem_bytes);
    dim3 gs((Hd + 15) / 16, Bd / 64, 2);
    for (int s = 0; s < Sd; s++)
        lstm_step<<<gs, 256, smem_bytes>>>(s, x, whhf, whhb);

    // Phase 3
    emis_kernel<<<Sd, Bd>>>(wproj, bproj);
    viterbi_kernel<<<2, 128>>>(start_t, end_t, trans, out);
}

// round 15
// speedup vs baseline: 1.0954x; 1.0659x over previous
#include <cuda_runtime.h>
#include <math.h>
#include <stdio.h>
#include <assert.h>

#define Vv 30000
#define Ee 300
#define Hd 300
#define G4 1200
#define Td 9
#define Bd 256
#define Sd 256

// ---- scratch (device globals) ----
__device__ float  g_table_f[(size_t)Vv * G4];
__device__ float  g_table_b[(size_t)Vv * G4];
__device__ float  g_hf[(size_t)Sd * Hd * Bd];   // [time][h][b]
__device__ float  g_hb[(size_t)Sd * Hd * Bd];
__device__ float  g_cf[Hd * Bd];                // [h][b]
__device__ float  g_cb[Hd * Bd];
__device__ double g_em[(size_t)Sd * Bd * Td];
__device__ unsigned char g_bp[(size_t)(Sd - 1) * Bd * Td];

__device__ __forceinline__ float clampg(float v) {
    return fmaxf(fminf(v, 30.f), -30.f);
}

struct SizePack { int n; int v[16]; };
__global__ void bad_layout_kernel(SizePack sp)
{
    printf("[diag] LAYOUT MISMATCH n_in=%d sizes:", sp.n);
    for (int i = 0; i < 16 && i < sp.n; i++) printf(" %d", sp.v[i]);
    printf("\n");
    assert(0);
}

// ============================================================
// Phase 1: vocab gate table, scalar FFMA, 128x128x16 tile, 8x8 micro.
// C[m][n] = sum_k A[m][k]*W[n][k] + b1[n]+b2[n]
// ============================================================
__global__ void __launch_bounds__(256)
table_gemm(const float* __restrict__ A,
           const float* __restrict__ Wf, const float* __restrict__ Wb,
           const float* __restrict__ b1f, const float* __restrict__ b2f,
           const float* __restrict__ b1b, const float* __restrict__ b2b)
{
    int dir = blockIdx.z;
    const float* W  = dir ? Wb  : Wf;
    const float* b1 = dir ? b1b : b1f;
    const float* b2 = dir ? b2b : b2f;
    float* C = dir ? g_table_b : g_table_f;

    __shared__ __align__(16) float As[16 * 132];
    __shared__ __align__(16) float Wsm[16 * 132];

    int n0 = blockIdx.x * 128;
    int m0 = blockIdx.y * 128;
    int tid = threadIdx.x;
    int tx = tid & 15;     // n octet
    int ty = tid >> 4;     // m octet
    int r  = tid & 127;
    int part = tid >> 7;   // 0/1 -> k half

    float acc[8][8] = {};

    for (int k0 = 0; k0 < Ee; k0 += 16) {
        __syncthreads();
        // stage A tile (transposed): As[k][m]
        {
            int m = m0 + r;
#pragma unroll
            for (int q = 0; q < 2; q++) {
                int k = k0 + part * 8 + q * 4;
                float4 v = make_float4(0.f, 0.f, 0.f, 0.f);
                if (m < Vv && k + 3 < Ee)
                    v = *(const float4*)&A[(size_t)m * Ee + k];
                int kk = part * 8 + q * 4;
                As[(kk + 0) * 132 + r] = v.x;
                As[(kk + 1) * 132 + r] = v.y;
                As[(kk + 2) * 132 + r] = v.z;
                As[(kk + 3) * 132 + r] = v.w;
            }
        }
        // stage W tile: Wsm[k][n]
        {
            int n = n0 + r;
#pragma unroll
            for (int q = 0; q < 2; q++) {
                int k = k0 + part * 8 + q * 4;
                float4 v = make_float4(0.f, 0.f, 0.f, 0.f);
                if (n < G4 && k + 3 < Ee)
                    v = *(const float4*)&W[(size_t)n * Ee + k];
                int kk = part * 8 + q * 4;
                Wsm[(kk + 0) * 132 + r] = v.x;
                Wsm[(kk + 1) * 132 + r] = v.y;
                Wsm[(kk + 2) * 132 + r] = v.z;
                Wsm[(kk + 3) * 132 + r] = v.w;
            }
        }
        __syncthreads();
#pragma unroll 4
        for (int kk = 0; kk < 16; kk++) {
            float4 a0 = *(const float4*)&As[kk * 132 + ty * 8];
            float4 a1 = *(const float4*)&As[kk * 132 + ty * 8 + 4];
            float4 w0 = *(const float4*)&Wsm[kk * 132 + tx * 8];
            float4 w1 = *(const float4*)&Wsm[kk * 132 + tx * 8 + 4];
            float av[8] = {a0.x, a0.y, a0.z, a0.w, a1.x, a1.y, a1.z, a1.w};
            float wv[8] = {w0.x, w0.y, w0.z, w0.w, w1.x, w1.y, w1.z, w1.w};
#pragma unroll
            for (int i = 0; i < 8; i++)
#pragma unroll
                for (int j = 0; j < 8; j++) acc[i][j] += av[i] * wv[j];
        }
    }

    int nb = n0 + tx * 8;
    float bias[8];
#pragma unroll
    for (int j = 0; j < 8; j++) {
        int n = nb + j;
        bias[j] = (n < G4) ? (b1[n] + b2[n]) : 0.f;
    }
#pragma unroll
    for (int i = 0; i < 8; i++) {
        int m = m0 + ty * 8 + i;
        if (m >= Vv) continue;
        if (nb + 7 < G4) {
            *(float4*)&C[(size_t)m * G4 + nb] =
                make_float4(acc[i][0] + bias[0], acc[i][1] + bias[1],
                            acc[i][2] + bias[2], acc[i][3] + bias[3]);
            *(float4*)&C[(size_t)m * G4 + nb + 4] =
                make_float4(acc[i][4] + bias[4], acc[i][5] + bias[5],
                            acc[i][6] + bias[6], acc[i][7] + bias[7]);
        } else {
#pragma unroll
            for (int j = 0; j < 8; j++)
                if (nb + j < G4) C[(size_t)m * G4 + nb + j] = acc[i][j] + bias[j];
        }
    }
}

// ============================================================
// Phase 2: one LSTM step, v5. Warp-per-h (8 h/block), lane = 2 b's.
// W reads are LDS.128 broadcasts; W staged [h][g][k] contiguously.
// 71.5KB smem -> 2 blocks/SM. grid (38,4,2)=304, 256 thr.
// ============================================================
__global__ void __launch_bounds__(256, 2)
lstm_step(int s, const int* __restrict__ x,
          const float* __restrict__ whhf, const float* __restrict__ whhb)
{
    extern __shared__ __align__(16) float smem[];
    float* Ws  = smem;           // [32 rows (hl*4+g)][304 k]  38,912B
    float* Hs0 = smem + 9728;    // [60][68]                   16,320B
    float* Hs1 = smem + 9728 + 4080;

    int dir = blockIdx.z;
    const float* whh = dir ? whhb : whhf;
    const float* tbl = dir ? g_table_b : g_table_f;
    float* hseq = dir ? g_hb : g_hf;
    float* cbuf = dir ? g_cb : g_cf;
    int time = dir ? (Sd - 1 - s) : s;

    int h0 = blockIdx.x * 8;
    int b0 = blockIdx.y * 64;
    int tid = threadIdx.x;
    int wid = tid >> 5;          // warp -> h
    int lane = tid & 31;         // lane -> 2 b's
    int h = h0 + wid;
    int hh = (h < Hd) ? h : (Hd - 1);
    int b_lo = b0 + 2 * lane;

    // token + table-row prefetch (consumed in epilogue)
    float tv[2][4];
#pragma unroll
    for (int e = 0; e < 2; e++) {
        int t = __ldg(&x[(b_lo + e) * Sd + time]);
        if ((unsigned)t >= (unsigned)Vv) t = 0;
        const float* trow = tbl + (size_t)t * G4 + hh;
#pragma unroll
        for (int g = 0; g < 4; g++) tv[e][g] = __ldg(trow + g * Hd);
    }

    float acc[2][4] = {};

    if (s > 0) {
        int ptime = dir ? (time + 1) : (time - 1);
        const float* hprev = hseq + (size_t)ptime * Hd * Bd + b0;

        // stage whole W tile contiguously: Ws[(hl*4+g)*304 + k]
#pragma unroll
        for (int l = 0; l < 10; l++) {
            int j = tid + l * 256;
            if (j < 2400) {
                int rrow = j / 75;          // 0..31 = hl*4+g
                int k4 = j % 75;
                int hl = rrow >> 2, g = rrow & 3;
                if (h0 + hl < Hd) {
                    float4 v = *(const float4*)&whh[((size_t)g * Hd + h0 + hl) * Hd + k4 * 4];
                    *(float4*)&Ws[rrow * 304 + k4 * 4] = v;
                }
            }
        }
        // stage H chunk 0
#pragma unroll
        for (int l = 0; l < 4; l++) {
            int j = tid + l * 256;
            if (j < 960) {
                int cc = j >> 4, rr = j & 15;
                *(float4*)&Hs0[cc * 68 + rr * 4] =
                    *(const float4*)&hprev[(size_t)cc * Bd + rr * 4];
            }
        }

        float* bufs[2] = {Hs0, Hs1};
        int cur = 0;
#pragma unroll
        for (int chunk = 0; chunk < 5; chunk++) {
            __syncthreads();
            if (chunk < 4) {
                const float* hp = hprev + (size_t)((chunk + 1) * 60) * Bd;
                float* dst = bufs[cur ^ 1];
#pragma unroll
                for (int l = 0; l < 4; l++) {
                    int j = tid + l * 256;
                    if (j < 960) {
                        int cc = j >> 4, rr = j & 15;
                        *(float4*)&dst[cc * 68 + rr * 4] =
                            *(const float4*)&hp[(size_t)cc * Bd + rr * 4];
                    }
                }
            }
            const float* wsb = Ws + (wid * 4) * 304 + chunk * 60;
            const float* hb  = bufs[cur] + 2 * lane;
#pragma unroll 5
            for (int k4 = 0; k4 < 15; k4++) {
                float4 w0 = *(const float4*)(wsb + k4 * 4);              // gate i
                float4 w1 = *(const float4*)(wsb + 304 + k4 * 4);        // gate f
                float4 w2 = *(const float4*)(wsb + 2 * 304 + k4 * 4);    // gate g
                float4 w3 = *(const float4*)(wsb + 3 * 304 + k4 * 4);    // gate o
                float2 hv0 = *(const float2*)(hb + (k4 * 4 + 0) * 68);
                float2 hv1 = *(const float2*)(hb + (k4 * 4 + 1) * 68);
                float2 hv2 = *(const float2*)(hb + (k4 * 4 + 2) * 68);
                float2 hv3 = *(const float2*)(hb + (k4 * 4 + 3) * 68);
                acc[0][0] += hv0.x * w0.x; acc[1][0] += hv0.y * w0.x;
                acc[0][1] += hv0.x * w1.x; acc[1][1] += hv0.y * w1.x;
                acc[0][2] += hv0.x * w2.x; acc[1][2] += hv0.y * w2.x;
                acc[0][3] += hv0.x * w3.x; acc[1][3] += hv0.y * w3.x;
                acc[0][0] += hv1.x * w0.y; acc[1][0] += hv1.y * w0.y;
                acc[0][1] += hv1.x * w1.y; acc[1][1] += hv1.y * w1.y;
                acc[0][2] += hv1.x * w2.y; acc[1][2] += hv1.y * w2.y;
                acc[0][3] += hv1.x * w3.y; acc[1][3] += hv1.y * w3.y;
                acc[0][0] += hv2.x * w0.z; acc[1][0] += hv2.y * w0.z;
                acc[0][1] += hv2.x * w1.z; acc[1][1] += hv2.y * w1.z;
                acc[0][2] += hv2.x * w2.z; acc[1][2] += hv2.y * w2.z;
                acc[0][3] += hv2.x * w3.z; acc[1][3] += hv2.y * w3.z;
                acc[0][0] += hv3.x * w0.w; acc[1][0] += hv3.y * w0.w;
                acc[0][1] += hv3.x * w1.w; acc[1][1] += hv3.y * w1.w;
                acc[0][2] += hv3.x * w2.w; acc[1][2] += hv3.y * w2.w;
                acc[0][3] += hv3.x * w3.w; acc[1][3] += hv3.y * w3.w;
            }
            cur ^= 1;
        }
    }

    // epilogue
    if (h < Hd) {
        float2 cold = make_float2(0.f, 0.f);
        if (s > 0) cold = *(const float2*)&cbuf[(size_t)h * Bd + b_lo];
        float coldA[2] = {cold.x, cold.y};
        float hnew[2], cnew[2];
#pragma unroll
        for (int e = 0; e < 2; e++) {
            float ai = clampg(acc[e][0] + tv[e][0]);
            float af = clampg(acc[e][1] + tv[e][1]);
            float ag = clampg(acc[e][2] + tv[e][2]);
            float ao = clampg(acc[e][3] + tv[e][3]);
            float ig = 1.f / (1.f + expf(-ai));
            float fg = 1.f / (1.f + expf(-af));
            float gg = tanhf(ag);
            float og = 1.f / (1.f + expf(-ao));
            float c = fg * coldA[e] + ig * gg;
            cnew[e] = c;
            hnew[e] = og * tanhf(clampg(c));
        }
        *(float2*)&cbuf[(size_t)h * Bd + b_lo] = make_float2(cnew[0], cnew[1]);
        *(float2*)&hseq[((size_t)time * Hd + h) * Bd + b_lo] =
            make_float2(hnew[0], hnew[1]);
    }
}

// ============================================================
// Phase 3a: emissions, fp64 accumulation. Block per s, thread per b.
// ============================================================
__global__ void __launch_bounds__(256)
emis_kernel(const float* __restrict__ wproj, const float* __restrict__ bproj)
{
    __shared__ float wp[Td * 2 * Hd];
    int s = blockIdx.x;
    int b = threadIdx.x;
    for (int i = threadIdx.x; i < Td * 2 * Hd; i += blockDim.x) wp[i] = wproj[i];
    __syncthreads();

    const float* f  = g_hf + (size_t)s * Hd * Bd;
    const float* bk = g_hb + (size_t)s * Hd * Bd;
    double acc[Td] = {};
    for (int j = 0; j < Hd; j++) {
        double v = (double)f[(size_t)j * Bd + b];
#pragma unroll
        for (int t = 0; t < Td; t++) acc[t] += v * (double)wp[t * 2 * Hd + j];
    }
    for (int j = 0; j < Hd; j++) {
        double v = (double)bk[(size_t)j * Bd + b];
#pragma unroll
        for (int t = 0; t < Td; t++) acc[t] += v * (double)wp[t * 2 * Hd + Hd + j];
    }
#pragma unroll
    for (int t = 0; t < Td; t++)
        g_em[((size_t)s * Bd + b) * Td + t] = acc[t] + (double)bproj[t];
}

// ============================================================
// Phase 3b: Viterbi DP + backtrack, fp64, float32 tag output.
// ============================================================
__global__ void viterbi_kernel(const float* __restrict__ start_t, const float* __restrict__ end_t,
                               const float* __restrict__ trans, float* __restrict__ out)
{
    __shared__ double tr[Td][Td];
    if (threadIdx.x < Td * Td)
        tr[threadIdx.x / Td][threadIdx.x % Td] = (double)trans[threadIdx.x];
    __syncthreads();
    int b = blockIdx.x * blockDim.x + threadIdx.x;
    if (b >= Bd) return;

    double sc[Td];
#pragma unroll
    for (int t = 0; t < Td; t++)
        sc[t] = (double)start_t[t] + g_em[(size_t)b * Td + t];

    for (int s = 1; s < Sd; s++) {
        const double* em = &g_em[((size_t)s * Bd + b) * Td];
        double ns[Td];
#pragma unroll
        for (int tn = 0; tn < Td; tn++) {
            double best = sc[0] + tr[0][tn];
            int arg = 0;
#pragma unroll
            for (int tp = 1; tp < Td; tp++) {
                double v = sc[tp] + tr[tp][tn];
                if (v > best) { best = v; arg = tp; }
            }
            ns[tn] = best + em[tn];
            g_bp[((size_t)(s - 1) * Bd + b) * Td + tn] = (unsigned char)arg;
        }
#pragma unroll
        for (int t = 0; t < Td; t++) sc[t] = ns[t];
    }

    int last = 0;
    double best = sc[0] + (double)end_t[0];
#pragma unroll
    for (int t = 1; t < Td; t++) {
        double v = sc[t] + (double)end_t[t];
        if (v > best) { best = v; last = t; }
    }
    out[b * Sd + (Sd - 1)] = (float)last;
    int tag = last;
    for (int s = Sd - 2; s >= 0; s--) {
        tag = g_bp[((size_t)s * Bd + b) * Td + tag];
        out[b * Sd + s] = (float)tag;
    }
}

// ============================================================
extern "C" void kernel_launch(void* const* d_in, const int* in_sizes, int n_in,
                              void* d_out, int out_size)
{
    static const int expA[15] = {65536, 9000000, 360000, 360000, 1200, 1200,
                                 360000, 360000, 1200, 1200, 5400, 9, 9, 9, 81};
    bool okA = (n_in == 15), okA4 = (n_in == 15);
    for (int i = 0; i < 15 && n_in == 15; i++) {
        if (in_sizes[i] != expA[i])     okA  = false;
        if (in_sizes[i] != expA[i] * 4) okA4 = false;
    }
    if (!okA && !okA4) {
        SizePack sp; sp.n = n_in;
        for (int i = 0; i < 16; i++) sp.v[i] = (i < n_in) ? in_sizes[i] : -1;
        bad_layout_kernel<<<1, 1>>>(sp);
        return;
    }

    const int*   x       = (const int*)  d_in[0];
    const float* emb     = (const float*)d_in[1];
    const float* wihf    = (const float*)d_in[2];
    const float* whhf    = (const float*)d_in[3];
    const float* bihf    = (const float*)d_in[4];
    const float* bhhf    = (const float*)d_in[5];
    const float* wihb    = (const float*)d_in[6];
    const float* whhb    = (const float*)d_in[7];
    const float* bihb    = (const float*)d_in[8];
    const float* bhhb    = (const float*)d_in[9];
    const float* wproj   = (const float*)d_in[10];
    const float* bproj   = (const float*)d_in[11];
    const float* start_t = (const float*)d_in[12];
    const float* end_t   = (const float*)d_in[13];
    const float* trans   = (const float*)d_in[14];
    float* out = (float*)d_out;

    // Phase 1: vocab gate tables
    dim3 gt((G4 + 127) / 128, (Vv + 127) / 128, 2);
    table_gemm<<<gt, 256>>>(emb, wihf, wihb, bihf, bhhf, bihb, bhhb);

    // Phase 2: 256 per-step launches
    int smem_bytes = (9728 + 2 * 4080) * sizeof(float);   // 71,552 B
    cudaFuncSetAttribute(lstm_step,
                         cudaFuncAttributeMaxDynamicSharedMemorySize, smem_bytes);
    dim3 gs(38, 4, 2);
    for (int s = 0; s < Sd; s++)
        lstm_step<<<gs, 256, smem_bytes>>>(s, x, whhf, whhb);

    // Phase 3
    emis_kernel<<<Sd, Bd>>>(wproj, bproj);
    viterbi_kernel<<<2, 128>>>(start_t, end_t, trans, out);
}